// round 15
// baseline (speedup 1.0000x reference)
#include <cuda_runtime.h>
#include <cuda_bf16.h>
#include <cuda_fp16.h>
#include <cstdint>

// ---------------------------------------------------------------------------
// GCN: out = relu(Â X W1 + b1) -> relu(Â H W2 + b2) -> @Wfc + bfc
// Aggregate-first + CSR gather; bf16 hi/lo mma.sync GEMM (3-term, ~1e-5);
// p2 activations stored fp16 -> layer-2 gather traffic halved (LTS-floor cut).
// ---------------------------------------------------------------------------

#define NMAX   50176
#define EMAX   1048576
#define F1     128
#define H      256

__device__ int   g_is64;
__device__ int   g_src   [EMAX];
__device__ int   g_dst   [EMAX];
__device__ int   g_cnt   [NMAX];
__device__ int   g_fill  [NMAX];
__device__ int   g_rowptr[NMAX];
__device__ int   g_eidx  [EMAX];
__device__ float g_dinv  [NMAX];
__device__ float g_p1  [(size_t)NMAX * F1];     // d[u]*x[u]  (fp32)
__device__ __align__(16) __half g_p2h[(size_t)NMAX * H];   // d[u]*h1[u] (fp16)

// pre-split bf16 operands (16B aligned for cp.async)
__device__ __align__(16) __nv_bfloat16 g_a1h[(size_t)NMAX * F1];
__device__ __align__(16) __nv_bfloat16 g_a1l[(size_t)NMAX * F1];
__device__ __align__(16) __nv_bfloat16 g_a2h[(size_t)NMAX * H];
__device__ __align__(16) __nv_bfloat16 g_a2l[(size_t)NMAX * H];
__device__ __align__(16) __nv_bfloat16 g_w1h[(size_t)H * F1];   // [n][K]
__device__ __align__(16) __nv_bfloat16 g_w1l[(size_t)H * F1];
__device__ __align__(16) __nv_bfloat16 g_w2h[(size_t)H * H];
__device__ __align__(16) __nv_bfloat16 g_w2l[(size_t)H * H];

__device__ __forceinline__ void split_bf16(float x, __nv_bfloat16& h, __nv_bfloat16& l) {
    h = __float2bfloat16_rn(x);
    l = __float2bfloat16_rn(x - __bfloat162float(h));
}

// --------------------------- edge ingest + init -----------------------------

__global__ void k_detect_init(const int* __restrict__ w, int n) {
    int i = blockIdx.x * blockDim.x + threadIdx.x;
    if (i < n) { g_cnt[i] = 0; g_fill[i] = 0; }
    if (blockIdx.x == 0) {
        __shared__ int any;
        if (threadIdx.x == 0) any = 0;
        __syncthreads();
        for (int j = threadIdx.x; j < 1024; j += blockDim.x)
            if (w[2 * j + 1] != 0) any = 1;
        __syncthreads();
        if (threadIdx.x == 0) g_is64 = (any == 0);
    }
}

__global__ void k_extract(const void* __restrict__ ei, int E, int n) {
    int i = blockIdx.x * blockDim.x + threadIdx.x;
    if (i >= 2 * E) return;
    long long v = g_is64 ? ((const long long*)ei)[i]
                         : (long long)((const int*)ei)[i];
    int c = (int)v;
    c = (c < 0) ? 0 : ((c >= n) ? n - 1 : c);
    if (i < E) {
        g_src[i] = c;
    } else {
        g_dst[i - E] = c;
        atomicAdd(&g_cnt[c], 1);
    }
}

// --------------------------- CSR build -------------------------------------

// single-block exclusive scan: thread t owns nodes [t*npt, t*npt+npt)
__global__ void k_scan(int n, int npt) {
    __shared__ int s[1024];
    int t = threadIdx.x;
    int base = t * npt;
    int sum = 0;
    for (int j = 0; j < npt; j++) {
        int idx = base + j;
        sum += (idx < n) ? g_cnt[idx] : 0;
    }
    s[t] = sum;
    __syncthreads();
    for (int off = 1; off < 1024; off <<= 1) {
        int x = (t >= off) ? s[t - off] : 0;
        __syncthreads();
        s[t] += x;
        __syncthreads();
    }
    int run = s[t] - sum;          // exclusive offset for this thread's range
    for (int j = 0; j < npt; j++) {
        int idx = base + j;
        if (idx < n) {
            g_rowptr[idx] = run;
            run += g_cnt[idx];
        }
    }
}

__global__ void k_fill(int E) {
    int e = blockIdx.x * blockDim.x + threadIdx.x;
    if (e >= E) return;
    int d = g_dst[e];
    int pos = g_rowptr[d] + atomicAdd(&g_fill[d], 1);
    g_eidx[pos] = g_src[e];
}

// --------------------------- node prep / W split ----------------------------

__global__ void k_prep(const float* __restrict__ x, int n) {
    int w = (blockIdx.x * blockDim.x + threadIdx.x) >> 5;
    if (w >= n) return;
    int lane = threadIdx.x & 31;
    float d = rsqrtf((float)(g_cnt[w] + 1));
    if (lane == 0) g_dinv[w] = d;
    float4 v = ((const float4*)(x + (size_t)w * F1))[lane];
    ((float4*)(g_p1 + (size_t)w * F1))[lane] =
        make_float4(v.x * d, v.y * d, v.z * d, v.w * d);
}

template <int K>
__global__ void k_splitW(const float* __restrict__ W,
                         __nv_bfloat16* __restrict__ Bh,
                         __nv_bfloat16* __restrict__ Bl) {
    int idx = blockIdx.x * blockDim.x + threadIdx.x;
    if (idx >= H * K) return;
    int c = idx / K, k = idx - c * K;
    __nv_bfloat16 h, l;
    split_bf16(W[(size_t)k * H + c], h, l);
    Bh[idx] = h;
    Bl[idx] = l;
}

// --------------------------- gather agg + fused split -----------------------

__global__ void k_agg1(int n) {
    int v = (blockIdx.x * blockDim.x + threadIdx.x) >> 5;
    if (v >= n) return;
    int lane = threadIdx.x & 31;
    float4 acc = ((const float4*)(g_p1 + (size_t)v * F1))[lane];
    int i = g_rowptr[v], end = i + g_cnt[v];
    for (; i + 1 < end; i += 2) {
        int u0 = g_eidx[i], u1 = g_eidx[i + 1];
        float4 m0 = ((const float4*)(g_p1 + (size_t)u0 * F1))[lane];
        float4 m1 = ((const float4*)(g_p1 + (size_t)u1 * F1))[lane];
        acc.x += m0.x + m1.x; acc.y += m0.y + m1.y;
        acc.z += m0.z + m1.z; acc.w += m0.w + m1.w;
    }
    if (i < end) {
        int u = g_eidx[i];
        float4 m = ((const float4*)(g_p1 + (size_t)u * F1))[lane];
        acc.x += m.x; acc.y += m.y; acc.z += m.z; acc.w += m.w;
    }
    float d = g_dinv[v];
    acc.x *= d; acc.y *= d; acc.z *= d; acc.w *= d;
    __nv_bfloat16 h0, l0, h1, l1, h2, l2, h3, l3;
    split_bf16(acc.x, h0, l0); split_bf16(acc.y, h1, l1);
    split_bf16(acc.z, h2, l2); split_bf16(acc.w, h3, l3);
    __nv_bfloat162* oh = (__nv_bfloat162*)(g_a1h + (size_t)v * F1);
    __nv_bfloat162* ol = (__nv_bfloat162*)(g_a1l + (size_t)v * F1);
    oh[lane * 2]     = __halves2bfloat162(h0, h1);
    oh[lane * 2 + 1] = __halves2bfloat162(h2, h3);
    ol[lane * 2]     = __halves2bfloat162(l0, l1);
    ol[lane * 2 + 1] = __halves2bfloat162(l2, l3);
}

__device__ __forceinline__ void add8h(float* a, uint4 m) {
    const __half2* p = (const __half2*)&m;
#pragma unroll
    for (int j = 0; j < 4; j++) {
        float2 f = __half22float2(p[j]);
        a[2 * j] += f.x;
        a[2 * j + 1] += f.y;
    }
}

// lane owns 8 contiguous elems (16B fp16) of the 256-wide row
__global__ void k_agg2(int n) {
    int v = (blockIdx.x * blockDim.x + threadIdx.x) >> 5;
    if (v >= n) return;
    int lane = threadIdx.x & 31;
    float acc[8] = {0, 0, 0, 0, 0, 0, 0, 0};
    add8h(acc, ((const uint4*)(g_p2h + (size_t)v * H))[lane]);   // self
    int i = g_rowptr[v], end = i + g_cnt[v];
    for (; i + 1 < end; i += 2) {
        int u0 = g_eidx[i], u1 = g_eidx[i + 1];
        uint4 m0 = ((const uint4*)(g_p2h + (size_t)u0 * H))[lane];
        uint4 m1 = ((const uint4*)(g_p2h + (size_t)u1 * H))[lane];
        add8h(acc, m0);
        add8h(acc, m1);
    }
    if (i < end) {
        int u = g_eidx[i];
        add8h(acc, ((const uint4*)(g_p2h + (size_t)u * H))[lane]);
    }
    float d = g_dinv[v];
    __nv_bfloat162* oh = (__nv_bfloat162*)(g_a2h + (size_t)v * H + lane * 8);
    __nv_bfloat162* ol = (__nv_bfloat162*)(g_a2l + (size_t)v * H + lane * 8);
#pragma unroll
    for (int j = 0; j < 4; j++) {
        __nv_bfloat16 h0, l0, h1, l1;
        split_bf16(acc[2 * j] * d, h0, l0);
        split_bf16(acc[2 * j + 1] * d, h1, l1);
        oh[j] = __halves2bfloat162(h0, h1);
        ol[j] = __halves2bfloat162(l0, l1);
    }
}

// ---------------------------------------------------------------------------
// mma.sync GEMM, full-width tiles: block 128(M) x 256(N), BK=32, 512 threads,
// 16 warps (4M x 4N), warp tile 32x64. Smem [row][40 bf16] (80B stride).
// EPI==1: p2h = fp16(d*relu(C+b1));  EPI==2: out[r] = relu(C+b2)@Wfc + bfc
// ---------------------------------------------------------------------------

#define A_TB   10240
#define B_TB   20480
#define B_BASE 40960
#define SMEM_GEMM (B_BASE + 4 * B_TB)   // 122880 bytes

__device__ __forceinline__ void mma_bf16(float* c, const uint32_t* a,
                                         uint32_t b0, uint32_t b1) {
    asm volatile(
        "mma.sync.aligned.m16n8k16.row.col.f32.bf16.bf16.f32 "
        "{%0,%1,%2,%3}, {%4,%5,%6,%7}, {%8,%9}, {%0,%1,%2,%3};\n"
        : "+f"(c[0]), "+f"(c[1]), "+f"(c[2]), "+f"(c[3])
        : "r"(a[0]), "r"(a[1]), "r"(a[2]), "r"(a[3]), "r"(b0), "r"(b1));
}

__device__ __forceinline__ void ldm_x4(uint32_t* r, uint32_t addr) {
    asm volatile(
        "ldmatrix.sync.aligned.m8n8.x4.shared.b16 {%0,%1,%2,%3}, [%4];\n"
        : "=r"(r[0]), "=r"(r[1]), "=r"(r[2]), "=r"(r[3]) : "r"(addr));
}

__device__ __forceinline__ void cpa16(uint32_t dst, const void* src) {
    asm volatile("cp.async.cg.shared.global [%0], [%1], 16;\n" :: "r"(dst), "l"(src));
}
__device__ __forceinline__ void cpa_commit() { asm volatile("cp.async.commit_group;\n"); }
template <int N>
__device__ __forceinline__ void cpa_wait() {
    asm volatile("cp.async.wait_group %0;\n" :: "n"(N));
}

template <int K, int EPI>
__global__ void __launch_bounds__(512)
k_gemm_tc(const __nv_bfloat16* __restrict__ Ah, const __nv_bfloat16* __restrict__ Al,
          const __nv_bfloat16* __restrict__ Bh, const __nv_bfloat16* __restrict__ Bl,
          const float* __restrict__ bias, const float* __restrict__ Wfc,
          const float* __restrict__ bfc, float* __restrict__ out, int M) {
    extern __shared__ __align__(16) char smem[];

    int tid = threadIdx.x, lane = tid & 31, warp = tid >> 5;
    int warpM = warp & 3, warpN = warp >> 2;           // 4 x 4
    int rowBase = blockIdx.x * 128;
    uint32_t sb = (uint32_t)__cvta_generic_to_shared(smem);

    float acc[2][8][4];
#pragma unroll
    for (int mf = 0; mf < 2; mf++)
#pragma unroll
        for (int nf = 0; nf < 8; nf++)
#pragma unroll
            for (int i = 0; i < 4; i++) acc[mf][nf][i] = 0.0f;

    auto load_stage = [&](int s, int k0) {
#pragma unroll
        for (int it = 0; it < 6; it++) {
            int id = tid + it * 512;                   // 0..3071
            if (id < 1024) {                           // A: 2 parts x 128r x 4c
                int p = id >> 9, rem = id & 511, r = rem >> 2, c = rem & 3;
                uint32_t dst = sb + (uint32_t)((s * 2 + p) * A_TB + r * 80 + c * 16);
                const __nv_bfloat16* src =
                    (p ? Al : Ah) + (size_t)(rowBase + r) * K + k0 + c * 8;
                cpa16(dst, src);
            } else {                                   // B: 2 parts x 256r x 4c
                int id2 = id - 1024;
                int p = id2 >> 10, rem = id2 & 1023, r = rem >> 2, c = rem & 3;
                uint32_t dst = sb + (uint32_t)(B_BASE + (s * 2 + p) * B_TB + r * 80 + c * 16);
                const __nv_bfloat16* src =
                    (p ? Bl : Bh) + (size_t)r * K + k0 + c * 8;
                cpa16(dst, src);
            }
        }
    };

    auto compute_stage = [&](int s) {
        uint32_t aBh = sb + (uint32_t)((s * 2 + 0) * A_TB);
        uint32_t aBl = sb + (uint32_t)((s * 2 + 1) * A_TB);
        uint32_t bBh = sb + (uint32_t)(B_BASE + (s * 2 + 0) * B_TB);
        uint32_t bBl = sb + (uint32_t)(B_BASE + (s * 2 + 1) * B_TB);
        uint32_t aoff = (uint32_t)(warpM * 32 + (lane & 15)) * 80 + (lane >> 4) * 16;
        uint32_t boff = (uint32_t)(warpN * 64 + ((lane >> 4) << 3) + (lane & 7)) * 80
                      + ((lane >> 3) & 1) * 16;
#pragma unroll
        for (int ks = 0; ks < 2; ks++) {
            uint32_t kb = ks * 32;
            uint32_t ah[2][4], al[2][4], bhf[4][4], blf[4][4];
#pragma unroll
            for (int mf = 0; mf < 2; mf++) {
                ldm_x4(ah[mf], aBh + aoff + mf * (16 * 80) + kb);
                ldm_x4(al[mf], aBl + aoff + mf * (16 * 80) + kb);
            }
#pragma unroll
            for (int nfp = 0; nfp < 4; nfp++) {
                ldm_x4(bhf[nfp], bBh + boff + nfp * (16 * 80) + kb);
                ldm_x4(blf[nfp], bBl + boff + nfp * (16 * 80) + kb);
            }
#pragma unroll
            for (int nf = 0; nf < 8; nf++) {
                uint32_t b0h = bhf[nf >> 1][(nf & 1) * 2], b1h = bhf[nf >> 1][(nf & 1) * 2 + 1];
                uint32_t b0l = blf[nf >> 1][(nf & 1) * 2], b1l = blf[nf >> 1][(nf & 1) * 2 + 1];
#pragma unroll
                for (int mf = 0; mf < 2; mf++) {
                    mma_bf16(acc[mf][nf], ah[mf], b0h, b1h);
                    mma_bf16(acc[mf][nf], ah[mf], b0l, b1l);
                    mma_bf16(acc[mf][nf], al[mf], b0h, b1h);
                }
            }
        }
    };

    const int T = K / 32;
    load_stage(0, 0);
    cpa_commit();
#pragma unroll 2
    for (int t = 0; t < T; t++) {
        if (t + 1 < T) {
            load_stage((t + 1) & 1, (t + 1) * 32);
            cpa_commit();
            cpa_wait<1>();
        } else {
            cpa_wait<0>();
        }
        __syncthreads();
        compute_stage(t & 1);
        __syncthreads();
    }

    // ---- epilogue
    if (EPI == 1) {
#pragma unroll
        for (int mf = 0; mf < 2; mf++)
#pragma unroll
            for (int rr = 0; rr < 2; rr++) {
                int r = rowBase + warpM * 32 + mf * 16 + (lane >> 2) + rr * 8;
                if (r >= M) continue;
                float d = g_dinv[r];
#pragma unroll
                for (int nf = 0; nf < 8; nf++) {
                    int c = warpN * 64 + nf * 8 + (lane & 3) * 2;
                    float v0 = fmaxf(acc[mf][nf][rr * 2 + 0] + bias[c], 0.f) * d;
                    float v1 = fmaxf(acc[mf][nf][rr * 2 + 1] + bias[c + 1], 0.f) * d;
                    *(__half2*)&g_p2h[(size_t)r * H + c] = __floats2half2_rn(v0, v1);
                }
            }
    } else {
        float* sred = (float*)smem;                 // 128 rows x 4 warpN partials
#pragma unroll
        for (int mf = 0; mf < 2; mf++)
#pragma unroll
            for (int rr = 0; rr < 2; rr++) {
                float p = 0.0f;
#pragma unroll
                for (int nf = 0; nf < 8; nf++) {
                    int c = warpN * 64 + nf * 8 + (lane & 3) * 2;
                    p += fmaxf(acc[mf][nf][rr * 2 + 0] + bias[c], 0.f) * Wfc[c];
                    p += fmaxf(acc[mf][nf][rr * 2 + 1] + bias[c + 1], 0.f) * Wfc[c + 1];
                }
                p += __shfl_xor_sync(0xFFFFFFFFu, p, 1);
                p += __shfl_xor_sync(0xFFFFFFFFu, p, 2);
                if ((lane & 3) == 0) {
                    int rl = warpM * 32 + mf * 16 + (lane >> 2) + rr * 8;
                    sred[rl * 4 + warpN] = p;
                }
            }
        __syncthreads();
        if (tid < 128) {
            int r = rowBase + tid;
            if (r < M)
                out[r] = sred[tid * 4] + sred[tid * 4 + 1]
                       + sred[tid * 4 + 2] + sred[tid * 4 + 3] + bfc[0];
        }
    }
}

// ---------------------------------------------------------------------------

extern "C" void kernel_launch(void* const* d_in, const int* in_sizes, int n_in,
                              void* d_out, int out_size) {
    const float* x   = (const float*)d_in[0];
    const void*  ei  = d_in[1];
    const float* W1  = (const float*)d_in[2];
    const float* b1  = (const float*)d_in[3];
    const float* W2  = (const float*)d_in[4];
    const float* b2  = (const float*)d_in[5];
    const float* Wfc = (const float*)d_in[6];
    const float* bfc = (const float*)d_in[7];
    float*       out = (float*)d_out;

    int h   = in_sizes[3];            // 256
    int fin = in_sizes[2] / h;        // 128
    int n   = in_sizes[0] / fin;      // 50000
    int E   = in_sizes[1] / 2;        // 800000
    (void)h; (void)n_in; (void)out_size;

    cudaFuncSetAttribute(k_gemm_tc<F1, 1>,
                         cudaFuncAttributeMaxDynamicSharedMemorySize, SMEM_GEMM);
    cudaFuncSetAttribute(k_gemm_tc<H, 2>,
                         cudaFuncAttributeMaxDynamicSharedMemorySize, SMEM_GEMM);

    __nv_bfloat16 *a1h, *a1l, *a2h, *a2l, *w1h, *w1l, *w2h, *w2l;
    cudaGetSymbolAddress((void**)&a1h, g_a1h);
    cudaGetSymbolAddress((void**)&a1l, g_a1l);
    cudaGetSymbolAddress((void**)&a2h, g_a2h);
    cudaGetSymbolAddress((void**)&a2l, g_a2l);
    cudaGetSymbolAddress((void**)&w1h, g_w1h);
    cudaGetSymbolAddress((void**)&w1l, g_w1l);
    cudaGetSymbolAddress((void**)&w2h, g_w2h);
    cudaGetSymbolAddress((void**)&w2l, g_w2l);

    int npt = (n + 1023) / 1024;      // 49

    k_detect_init<<<(n + 255) / 256, 256>>>((const int*)ei, n);
    k_extract<<<(2 * E + 255) / 256, 256>>>(ei, E, n);
    k_scan<<<1, 1024>>>(n, npt);
    k_fill<<<(E + 255) / 256, 256>>>(E);

    k_splitW<F1><<<(H * F1 + 255) / 256, 256>>>(W1, w1h, w1l);
    k_splitW<H> <<<(H * H  + 255) / 256, 256>>>(W2, w2h, w2l);

    k_prep<<<(n * 32 + 255) / 256, 256>>>(x, n);
    k_agg1<<<(n * 32 + 255) / 256, 256>>>(n);

    int gblocks = (n + 127) / 128;
    k_gemm_tc<F1, 1><<<gblocks, 512, SMEM_GEMM>>>(a1h, a1l, w1h, w1l, b1, nullptr, nullptr, nullptr, n);
    k_agg2<<<(n * 32 + 255) / 256, 256>>>(n);
    k_gemm_tc<H, 2><<<gblocks, 512, SMEM_GEMM>>>(a2h, a2l, w2h, w2l, b2, Wfc, bfc, out, n);
}